// round 5
// baseline (speedup 1.0000x reference)
#include <cuda_runtime.h>
#include <cstdint>

#define MAXN 100000
#define MAXE 3200000
#define FDIM 128   // IN == OUT == 128

// Scratch (device globals: allocation-free per harness rules)
__device__ float g_h[(size_t)MAXN * FDIM];   // h = x @ W   (51.2 MB)
__device__ float g_dis[MAXN];                // rsqrt(deg_in + 1)
__device__ int   g_deg[MAXN];                // incoming-edge count (excl. self-loop)
__device__ int   g_start[MAXN];              // CSR bin start
__device__ int   g_cur[MAXN];                // fill cursor
__device__ int   g_csr[MAXE];                // src index per binned edge
__device__ int   g_cursor;                   // global reservation cursor
__device__ int   g_is32;                     // 1 if edge_index is int32, 0 if int64

// ---------------------------------------------------------------------------
// 0) dtype probe: interpret first 64 words as int64; if any lands outside
//    [0, n) the buffer must be int32 (pairs packed per 8 bytes).
__global__ void k_detect(const void* __restrict__ ei, int n) {
    if (blockIdx.x == 0 && threadIdx.x == 0) {
        const long long* p = (const long long*)ei;
        int is32 = 0;
        for (int i = 0; i < 64; i++) {
            long long v = p[i];
            if (v < 0 || v >= (long long)n) { is32 = 1; break; }
        }
        g_is32 = is32;
        g_cursor = 0;
    }
}

// dtype-agnostic index load: logical element idx of the flat [2*E] array
__device__ __forceinline__ int load_idx(const void* p, long long idx, int is32) {
    if (is32) return ((const int*)p)[idx];
    return (int)((const long long*)p)[idx];
}

// ---------------------------------------------------------------------------
// 1) reset degree
__global__ void k_deg_init(int n) {
    int i = blockIdx.x * blockDim.x + threadIdx.x;
    if (i < n) g_deg[i] = 0;
}

// 2) histogram over dst (elements [e, 2e) of edge_index)
__global__ void k_deg(const void* __restrict__ ei, int e, int n) {
    int i = blockIdx.x * blockDim.x + threadIdx.x;
    if (i < e) {
        int d = load_idx(ei, (long long)e + i, g_is32);
        if ((unsigned)d < (unsigned)n) atomicAdd(&g_deg[d], 1);
    }
}

// 3) reserve CSR bins + compute dis = rsqrt(deg + 1)  (+1 = self-loop)
__global__ void k_reserve(int n) {
    int i = blockIdx.x * blockDim.x + threadIdx.x;
    if (i < n) {
        int d = g_deg[i];
        int st = atomicAdd(&g_cursor, d);
        g_start[i] = st;
        g_cur[i]   = st;
        g_dis[i]   = rsqrtf((float)(d + 1));
    }
}

// 4) fill CSR: bin src indices by dst
__global__ void k_fill(const void* __restrict__ ei, int e, int n) {
    int i = blockIdx.x * blockDim.x + threadIdx.x;
    if (i < e) {
        int is32 = g_is32;
        int s = load_idx(ei, i, is32);
        int d = load_idx(ei, (long long)e + i, is32);
        if ((unsigned)d < (unsigned)n && (unsigned)s < (unsigned)n) {
            int pos = atomicAdd(&g_cur[d], 1);
            g_csr[pos] = s;
        }
    }
}

// ---------------------------------------------------------------------------
// 5) GEMM: g_h = x @ W.  256 threads, 64 rows/block, reg tile 8x4 per thread.
__global__ void k_gemm(const float* __restrict__ x, const float* __restrict__ W, int n) {
    extern __shared__ float sm[];
    float* Ws = sm;                 // [128][128] = 64 KB
    float* Xs = sm + FDIM * FDIM;   // [64][128]  = 32 KB

    const int row0 = blockIdx.x * 64;

    for (int i = threadIdx.x; i < FDIM * FDIM / 4; i += 256)
        ((float4*)Ws)[i] = ((const float4*)W)[i];

    for (int i = threadIdx.x; i < 64 * FDIM / 4; i += 256) {
        int r = (i * 4) >> 7;
        int gr = row0 + r;
        float4 v = make_float4(0.f, 0.f, 0.f, 0.f);
        if (gr < n) v = ((const float4*)(x + (size_t)gr * FDIM))[i & 31];
        ((float4*)Xs)[i] = v;
    }
    __syncthreads();

    const int cidx = threadIdx.x & 31;   // 32 groups of 4 cols
    const int ridx = threadIdx.x >> 5;   // 8 groups of 8 rows

    float acc[8][4];
#pragma unroll
    for (int r = 0; r < 8; r++) { acc[r][0] = acc[r][1] = acc[r][2] = acc[r][3] = 0.f; }

#pragma unroll 4
    for (int k = 0; k < FDIM; k++) {
        float4 w = ((const float4*)(Ws + (size_t)k * FDIM))[cidx];
#pragma unroll
        for (int r = 0; r < 8; r++) {
            float xv = Xs[(ridx * 8 + r) * FDIM + k];
            acc[r][0] = fmaf(xv, w.x, acc[r][0]);
            acc[r][1] = fmaf(xv, w.y, acc[r][1]);
            acc[r][2] = fmaf(xv, w.z, acc[r][2]);
            acc[r][3] = fmaf(xv, w.w, acc[r][3]);
        }
    }

#pragma unroll
    for (int r = 0; r < 8; r++) {
        int gr = row0 + ridx * 8 + r;
        if (gr < n) {
            float4 v = make_float4(acc[r][0], acc[r][1], acc[r][2], acc[r][3]);
            ((float4*)(g_h + (size_t)gr * FDIM))[cidx] = v;
        }
    }
}

// ---------------------------------------------------------------------------
// 6) gather: one warp per node. Register accumulation, single write.
//    out[i] = relu( dis[i] * ( dis[i]*h[i] + sum_{s in bin(i)} dis[s]*h[s] ) + b )
__global__ void k_gather(const float* __restrict__ b, float* __restrict__ out, int n) {
    int warp = (blockIdx.x * blockDim.x + threadIdx.x) >> 5;
    int lane = threadIdx.x & 31;
    if (warp >= n) return;

    const float4* __restrict__ h4 = (const float4*)g_h;

    float di  = g_dis[warp];
    int   s0  = g_start[warp];
    int   deg = g_deg[warp];

    // self-loop term: dis[i] * h[i]
    float4 v = h4[(size_t)warp * 32 + lane];
    float4 acc = make_float4(di * v.x, di * v.y, di * v.z, di * v.w);

    for (int base = 0; base < deg; base += 32) {
        int m = deg - base;
        if (m > 32) m = 32;
        int   s = 0;
        float w = 0.f;
        if (lane < m) {
            s = g_csr[s0 + base + lane];   // coalesced
            w = g_dis[s];
        }
#pragma unroll 4
        for (int j = 0; j < m; j++) {
            int   sj = __shfl_sync(0xffffffffu, s, j);
            float wj = __shfl_sync(0xffffffffu, w, j);
            float4 hv = h4[(size_t)sj * 32 + lane];   // L2-resident row
            acc.x = fmaf(wj, hv.x, acc.x);
            acc.y = fmaf(wj, hv.y, acc.y);
            acc.z = fmaf(wj, hv.z, acc.z);
            acc.w = fmaf(wj, hv.w, acc.w);
        }
    }

    float4 bb = ((const float4*)b)[lane];
    float4 o;
    o.x = fmaxf(fmaf(di, acc.x, bb.x), 0.f);
    o.y = fmaxf(fmaf(di, acc.y, bb.y), 0.f);
    o.z = fmaxf(fmaf(di, acc.z, bb.z), 0.f);
    o.w = fmaxf(fmaf(di, acc.w, bb.w), 0.f);
    ((float4*)out)[(size_t)warp * 32 + lane] = o;
}

// ---------------------------------------------------------------------------
extern "C" void kernel_launch(void* const* d_in, const int* in_sizes, int n_in,
                              void* d_out, int out_size) {
    const float* x   = (const float*)d_in[0];
    const void*  ei  = d_in[1];            // [2, E] int32 or int64 (probed)
    const float* W   = (const float*)d_in[2];
    const float* b   = (const float*)d_in[3];
    float*       out = (float*)d_out;

    const int n = in_sizes[0] / FDIM;      // 100000
    const int e = in_sizes[1] / 2;         // 3200000

    // dtype probe + CSR build
    k_detect<<<1, 32>>>(ei, n);
    k_deg_init<<<(n + 255) / 256, 256>>>(n);
    k_deg<<<(e + 255) / 256, 256>>>(ei, e, n);
    k_reserve<<<(n + 255) / 256, 256>>>(n);
    k_fill<<<(e + 255) / 256, 256>>>(ei, e, n);

    // h = x @ W (96 KB dynamic smem)
    static const size_t smem = (size_t)(FDIM * FDIM + 64 * FDIM) * sizeof(float);
    cudaFuncSetAttribute(k_gemm, cudaFuncAttributeMaxDynamicSharedMemorySize, (int)smem);
    k_gemm<<<(n + 63) / 64, 256, smem>>>(x, W, n);

    // fused gather + self-loop + bias + relu (one warp per node)
    long long threads_total = (long long)n * 32;
    k_gather<<<(int)((threads_total + 255) / 256), 256>>>(b, out, n);
}

// round 6
// speedup vs baseline: 1.1394x; 1.1394x over previous
#include <cuda_runtime.h>
#include <cstdint>

#define MAXN 100000
#define MAXE 3200000
#define FDIM 128   // IN == OUT == 128

// Scratch (device globals: allocation-free per harness rules)
__device__ float g_h[(size_t)MAXN * FDIM];   // h' = dis .* (x @ W)   (51.2 MB)
__device__ float g_dis[MAXN];                // rsqrt(deg_in + 1)
__device__ int   g_deg[MAXN];                // incoming-edge count (excl. self-loop)
__device__ int   g_start[MAXN];              // CSR bin start
__device__ int   g_cur[MAXN];                // fill cursor
__device__ int   g_csr[MAXE];                // src index per binned edge
__device__ int   g_cursor;                   // global reservation cursor
__device__ int   g_is32;                     // 1 if edge_index is int32, 0 if int64

// ---------------------------------------------------------------------------
// 0) dtype probe (int32 vs int64 edge_index) + cursor reset
__global__ void k_detect(const void* __restrict__ ei, int n) {
    if (blockIdx.x == 0 && threadIdx.x == 0) {
        const long long* p = (const long long*)ei;
        int is32 = 0;
        for (int i = 0; i < 64; i++) {
            long long v = p[i];
            if (v < 0 || v >= (long long)n) { is32 = 1; break; }
        }
        g_is32 = is32;
        g_cursor = 0;
    }
}

__device__ __forceinline__ int load_idx(const void* p, long long idx, int is32) {
    if (is32) return ((const int*)p)[idx];
    return (int)((const long long*)p)[idx];
}

// 1) reset degree
__global__ void k_deg_init(int n) {
    int i = blockIdx.x * blockDim.x + threadIdx.x;
    if (i < n) g_deg[i] = 0;
}

// 2) histogram over dst
__global__ void k_deg(const void* __restrict__ ei, int e, int n) {
    int i = blockIdx.x * blockDim.x + threadIdx.x;
    if (i < e) {
        int d = load_idx(ei, (long long)e + i, g_is32);
        if ((unsigned)d < (unsigned)n) atomicAdd(&g_deg[d], 1);
    }
}

// 3) reserve CSR bins + dis = rsqrt(deg + 1)
__global__ void k_reserve(int n) {
    int i = blockIdx.x * blockDim.x + threadIdx.x;
    if (i < n) {
        int d = g_deg[i];
        int st = atomicAdd(&g_cursor, d);
        g_start[i] = st;
        g_cur[i]   = st;
        g_dis[i]   = rsqrtf((float)(d + 1));
    }
}

// 4) fill CSR
__global__ void k_fill(const void* __restrict__ ei, int e, int n) {
    int i = blockIdx.x * blockDim.x + threadIdx.x;
    if (i < e) {
        int is32 = g_is32;
        int s = load_idx(ei, i, is32);
        int d = load_idx(ei, (long long)e + i, is32);
        if ((unsigned)d < (unsigned)n && (unsigned)s < (unsigned)n) {
            int pos = atomicAdd(&g_cur[d], 1);
            g_csr[pos] = s;
        }
    }
}

// ---------------------------------------------------------------------------
// 5) GEMM via tf32 mma.sync (m16n8k8), 128x128x128 per block, 256 threads.
//    A and B are staged in smem PRE-SWIZZLED into fragment layout so the
//    mainloop does conflict-free LDS.128 / LDS.64 only.
//    Epilogue scales row r by g_dis[r]:  g_h[r] = dis[r] * (x@W)[r].
//
//    m16n8k8 fragment maps (groupID = lane>>2, tig = lane&3):
//      A (row-major): a0=(g,     tig)  a1=(g+8,   tig)  a2=(g,   tig+4)  a3=(g+8, tig+4)
//      B (col-major): b0=(k=tig, n=g)  b1=(k=tig+4, n=g)
//      C:             c0=(g, 2tig) c1=(g, 2tig+1) c2=(g+8, 2tig) c3=(g+8, 2tig+1)
__global__ void k_gemm_tf32(const float* __restrict__ x, const float* __restrict__ W, int n) {
    extern __shared__ uint32_t sm[];
    uint32_t* A = sm;            // [16 ks][8 w][32 lane][4 reg]  = 64 KB
    uint32_t* B = sm + 16384;    // [16 ks][16 nt][32 lane][2 reg] = 64 KB

    const int row0 = blockIdx.x * 128;
    const int tid  = threadIdx.x;

    // --- stage A fragments (x tile rows row0..row0+127, full K) ---
    for (int i = tid; i < 16 * 8 * 32; i += 256) {
        int lane = i & 31;
        int w    = (i >> 5) & 7;
        int ks   = i >> 8;
        int r    = row0 + w * 16 + (lane >> 2);
        int c    = ks * 8 + (lane & 3);
        float v0 = 0.f, v1 = 0.f, v2 = 0.f, v3 = 0.f;
        if (r < n)     { v0 = x[(size_t)r * FDIM + c];       v2 = x[(size_t)r * FDIM + c + 4]; }
        if (r + 8 < n) { v1 = x[(size_t)(r + 8) * FDIM + c]; v3 = x[(size_t)(r + 8) * FDIM + c + 4]; }
        uint32_t t0, t1, t2, t3;
        asm("cvt.rna.tf32.f32 %0, %1;" : "=r"(t0) : "f"(v0));
        asm("cvt.rna.tf32.f32 %0, %1;" : "=r"(t1) : "f"(v1));
        asm("cvt.rna.tf32.f32 %0, %1;" : "=r"(t2) : "f"(v2));
        asm("cvt.rna.tf32.f32 %0, %1;" : "=r"(t3) : "f"(v3));
        *(uint4*)&A[(size_t)i * 4] = make_uint4(t0, t1, t2, t3);
    }

    // --- stage B fragments (full 128x128 W) ---
    for (int i = tid; i < 16 * 16 * 32; i += 256) {
        int lane = i & 31;
        int nt   = (i >> 5) & 15;
        int ks   = i >> 9;
        int k    = ks * 8 + (lane & 3);
        int c    = nt * 8 + (lane >> 2);
        float v0 = W[(size_t)k * FDIM + c];
        float v1 = W[(size_t)(k + 4) * FDIM + c];
        uint32_t t0, t1;
        asm("cvt.rna.tf32.f32 %0, %1;" : "=r"(t0) : "f"(v0));
        asm("cvt.rna.tf32.f32 %0, %1;" : "=r"(t1) : "f"(v1));
        *(uint2*)&B[(size_t)i * 2] = make_uint2(t0, t1);
    }
    __syncthreads();

    const int lane = tid & 31;
    const int w    = tid >> 5;

    float acc[16][4];
#pragma unroll
    for (int nt = 0; nt < 16; nt++) { acc[nt][0] = acc[nt][1] = acc[nt][2] = acc[nt][3] = 0.f; }

#pragma unroll
    for (int ks = 0; ks < 16; ks++) {
        uint4 a = *(const uint4*)&A[(((ks * 8 + w) * 32 + lane)) * 4];
#pragma unroll
        for (int nt = 0; nt < 16; nt++) {
            uint2 b = *(const uint2*)&B[(((ks * 16 + nt) * 32 + lane)) * 2];
            asm volatile(
                "mma.sync.aligned.m16n8k8.row.col.f32.tf32.tf32.f32 "
                "{%0,%1,%2,%3}, {%4,%5,%6,%7}, {%8,%9}, {%0,%1,%2,%3};"
                : "+f"(acc[nt][0]), "+f"(acc[nt][1]), "+f"(acc[nt][2]), "+f"(acc[nt][3])
                : "r"(a.x), "r"(a.y), "r"(a.z), "r"(a.w), "r"(b.x), "r"(b.y));
        }
    }

    // --- epilogue: scale by dis[row], write g_h ---
    int r0 = row0 + w * 16 + (lane >> 2);
    int cb = 2 * (lane & 3);
    if (r0 < n) {
        float d = g_dis[r0];
        float* p = g_h + (size_t)r0 * FDIM + cb;
#pragma unroll
        for (int nt = 0; nt < 16; nt++) {
            float2 v = make_float2(d * acc[nt][0], d * acc[nt][1]);
            *(float2*)(p + nt * 8) = v;
        }
    }
    if (r0 + 8 < n) {
        float d = g_dis[r0 + 8];
        float* p = g_h + (size_t)(r0 + 8) * FDIM + cb;
#pragma unroll
        for (int nt = 0; nt < 16; nt++) {
            float2 v = make_float2(d * acc[nt][2], d * acc[nt][3]);
            *(float2*)(p + nt * 8) = v;
        }
    }
}

// ---------------------------------------------------------------------------
// 6) gather: one warp per node. h' rows are pre-scaled by dis[src], so the
//    inner loop is a pure sum. out = relu(dis[i]*(h'[i] + sum h'[s]) + b).
__global__ void k_gather(const float* __restrict__ b, float* __restrict__ out, int n) {
    int node = (blockIdx.x * blockDim.x + threadIdx.x) >> 5;
    int lane = threadIdx.x & 31;
    if (node >= n) return;

    const float4* __restrict__ h4 = (const float4*)g_h;

    float di  = g_dis[node];
    int   s0  = g_start[node];
    int   deg = g_deg[node];

    // self-loop: contributes h'[i] (final *di gives dis^2 * h[i])
    float4 acc = h4[(size_t)node * 32 + lane];

    for (int base = 0; base < deg; base += 32) {
        int m = deg - base;
        if (m > 32) m = 32;
        int s = (lane < m) ? g_csr[s0 + base + lane] : 0;   // coalesced
#pragma unroll 4
        for (int j = 0; j < m; j++) {
            int sj = __shfl_sync(0xffffffffu, s, j);
            float4 hv = h4[(size_t)sj * 32 + lane];          // L2-resident row
            acc.x += hv.x; acc.y += hv.y; acc.z += hv.z; acc.w += hv.w;
        }
    }

    float4 bb = ((const float4*)b)[lane];
    float4 o;
    o.x = fmaxf(fmaf(di, acc.x, bb.x), 0.f);
    o.y = fmaxf(fmaf(di, acc.y, bb.y), 0.f);
    o.z = fmaxf(fmaf(di, acc.z, bb.z), 0.f);
    o.w = fmaxf(fmaf(di, acc.w, bb.w), 0.f);
    ((float4*)out)[(size_t)node * 32 + lane] = o;
}

// ---------------------------------------------------------------------------
extern "C" void kernel_launch(void* const* d_in, const int* in_sizes, int n_in,
                              void* d_out, int out_size) {
    const float* x   = (const float*)d_in[0];
    const void*  ei  = d_in[1];            // [2, E] int32 or int64 (probed)
    const float* W   = (const float*)d_in[2];
    const float* b   = (const float*)d_in[3];
    float*       out = (float*)d_out;

    const int n = in_sizes[0] / FDIM;      // 100000
    const int e = in_sizes[1] / 2;         // 3200000

    // CSR build + normalization (dis needed by GEMM epilogue)
    k_detect<<<1, 32>>>(ei, n);
    k_deg_init<<<(n + 255) / 256, 256>>>(n);
    k_deg<<<(e + 255) / 256, 256>>>(ei, e, n);
    k_reserve<<<(n + 255) / 256, 256>>>(n);
    k_fill<<<(e + 255) / 256, 256>>>(ei, e, n);

    // h' = dis .* (x @ W)   (tf32 tensor-core GEMM, 128 KB dynamic smem)
    static const int smem = 128 * 1024;
    cudaFuncSetAttribute(k_gemm_tf32, cudaFuncAttributeMaxDynamicSharedMemorySize, smem);
    k_gemm_tf32<<<(n + 127) / 128, 256, smem>>>(x, W, n);

    // fused gather + self-loop + bias + relu (one warp per node)
    long long threads_total = (long long)n * 32;
    k_gather<<<(int)((threads_total + 255) / 256), 256>>>(b, out, n);
}

// round 7
// speedup vs baseline: 1.3509x; 1.1856x over previous
#include <cuda_runtime.h>
#include <cuda_fp16.h>
#include <cstdint>

#define MAXN 100000
#define MAXE 3200000
#define FDIM 128   // IN == OUT == 128

// Scratch (device globals: allocation-free per harness rules)
__device__ __half g_h[(size_t)MAXN * FDIM];  // h' = dis .* (x @ W)  (25.6 MB, fp16)
__device__ float  g_dis[MAXN];               // rsqrt(deg_in + 1)
__device__ int    g_deg[MAXN];               // incoming-edge count (excl. self-loop)
__device__ int    g_start[MAXN];             // CSR bin start
__device__ int    g_cur[MAXN];               // fill cursor
__device__ int    g_csr[MAXE];               // src index per binned edge
__device__ int    g_cursor;                  // global reservation cursor
__device__ int    g_is32;                    // 1 if edge_index is int32, 0 if int64

// ---------------------------------------------------------------------------
// 1) reset degree + dtype probe (fused): thread 0 probes 64 int64 words; any
//    value outside [0, n) means the buffer is int32-packed.
__global__ void k_init(const void* __restrict__ ei, int n) {
    int i = blockIdx.x * blockDim.x + threadIdx.x;
    if (i < n) g_deg[i] = 0;
    if (i == 0) {
        const long long* p = (const long long*)ei;
        int is32 = 0;
        for (int k = 0; k < 64; k++) {
            long long v = p[k];
            if (v < 0 || v >= (long long)n) { is32 = 1; break; }
        }
        g_is32 = is32;
        g_cursor = 0;
    }
}

__device__ __forceinline__ int load_idx(const void* p, long long idx, int is32) {
    if (is32) return ((const int*)p)[idx];
    return (int)((const long long*)p)[idx];
}

// 2) histogram over dst
__global__ void k_deg(const void* __restrict__ ei, int e, int n) {
    int i = blockIdx.x * blockDim.x + threadIdx.x;
    if (i < e) {
        int d = load_idx(ei, (long long)e + i, g_is32);
        if ((unsigned)d < (unsigned)n) atomicAdd(&g_deg[d], 1);
    }
}

// 3) reserve CSR bins + dis = rsqrt(deg + 1)
__global__ void k_reserve(int n) {
    int i = blockIdx.x * blockDim.x + threadIdx.x;
    if (i < n) {
        int d = g_deg[i];
        int st = atomicAdd(&g_cursor, d);
        g_start[i] = st;
        g_cur[i]   = st;
        g_dis[i]   = rsqrtf((float)(d + 1));
    }
}

// 4) fill CSR
__global__ void k_fill(const void* __restrict__ ei, int e, int n) {
    int i = blockIdx.x * blockDim.x + threadIdx.x;
    if (i < e) {
        int is32 = g_is32;
        int s = load_idx(ei, i, is32);
        int d = load_idx(ei, (long long)e + i, is32);
        if ((unsigned)d < (unsigned)n && (unsigned)s < (unsigned)n) {
            int pos = atomicAdd(&g_cur[d], 1);
            g_csr[pos] = s;
        }
    }
}

// ---------------------------------------------------------------------------
// 5) GEMM via tf32 mma.sync (m16n8k8), 128x128x128 per block, 256 threads.
//    A/B staged in smem pre-swizzled to fragment layout (conflict-free LDS).
//    Epilogue: g_h[r] = fp16( dis[r] * (x@W)[r] ).
__global__ void k_gemm_tf32(const float* __restrict__ x, const float* __restrict__ W, int n) {
    extern __shared__ uint32_t sm[];
    uint32_t* A = sm;            // [16 ks][8 w][32 lane][4 reg]   = 64 KB
    uint32_t* B = sm + 16384;    // [16 ks][16 nt][32 lane][2 reg] = 64 KB

    const int row0 = blockIdx.x * 128;
    const int tid  = threadIdx.x;

    // stage A fragments (x rows row0..row0+127, full K)
    for (int i = tid; i < 16 * 8 * 32; i += 256) {
        int lane = i & 31;
        int w    = (i >> 5) & 7;
        int ks   = i >> 8;
        int r    = row0 + w * 16 + (lane >> 2);
        int c    = ks * 8 + (lane & 3);
        float v0 = 0.f, v1 = 0.f, v2 = 0.f, v3 = 0.f;
        if (r < n)     { v0 = x[(size_t)r * FDIM + c];       v2 = x[(size_t)r * FDIM + c + 4]; }
        if (r + 8 < n) { v1 = x[(size_t)(r + 8) * FDIM + c]; v3 = x[(size_t)(r + 8) * FDIM + c + 4]; }
        uint32_t t0, t1, t2, t3;
        asm("cvt.rna.tf32.f32 %0, %1;" : "=r"(t0) : "f"(v0));
        asm("cvt.rna.tf32.f32 %0, %1;" : "=r"(t1) : "f"(v1));
        asm("cvt.rna.tf32.f32 %0, %1;" : "=r"(t2) : "f"(v2));
        asm("cvt.rna.tf32.f32 %0, %1;" : "=r"(t3) : "f"(v3));
        *(uint4*)&A[(size_t)i * 4] = make_uint4(t0, t1, t2, t3);
    }

    // stage B fragments (full 128x128 W)
    for (int i = tid; i < 16 * 16 * 32; i += 256) {
        int lane = i & 31;
        int nt   = (i >> 5) & 15;
        int ks   = i >> 9;
        int k    = ks * 8 + (lane & 3);
        int c    = nt * 8 + (lane >> 2);
        float v0 = W[(size_t)k * FDIM + c];
        float v1 = W[(size_t)(k + 4) * FDIM + c];
        uint32_t t0, t1;
        asm("cvt.rna.tf32.f32 %0, %1;" : "=r"(t0) : "f"(v0));
        asm("cvt.rna.tf32.f32 %0, %1;" : "=r"(t1) : "f"(v1));
        *(uint2*)&B[(size_t)i * 2] = make_uint2(t0, t1);
    }
    __syncthreads();

    const int lane = tid & 31;
    const int w    = tid >> 5;

    float acc[16][4];
#pragma unroll
    for (int nt = 0; nt < 16; nt++) { acc[nt][0] = acc[nt][1] = acc[nt][2] = acc[nt][3] = 0.f; }

#pragma unroll
    for (int ks = 0; ks < 16; ks++) {
        uint4 a = *(const uint4*)&A[(((ks * 8 + w) * 32 + lane)) * 4];
#pragma unroll
        for (int nt = 0; nt < 16; nt++) {
            uint2 b = *(const uint2*)&B[(((ks * 16 + nt) * 32 + lane)) * 2];
            asm volatile(
                "mma.sync.aligned.m16n8k8.row.col.f32.tf32.tf32.f32 "
                "{%0,%1,%2,%3}, {%4,%5,%6,%7}, {%8,%9}, {%0,%1,%2,%3};"
                : "+f"(acc[nt][0]), "+f"(acc[nt][1]), "+f"(acc[nt][2]), "+f"(acc[nt][3])
                : "r"(a.x), "r"(a.y), "r"(a.z), "r"(a.w), "r"(b.x), "r"(b.y));
        }
    }

    // epilogue: scale by dis[row], convert to fp16, write g_h
    // C frag: c0=(g,2t) c1=(g,2t+1) -> adjacent cols = one __half2
    int r0 = row0 + w * 16 + (lane >> 2);
    int cp = lane & 3;                       // half2 index within an 8-col group
    if (r0 < n) {
        float d = g_dis[r0];
        __half2* p = (__half2*)(g_h + (size_t)r0 * FDIM) + cp;
#pragma unroll
        for (int nt = 0; nt < 16; nt++)
            p[nt * 4] = __floats2half2_rn(d * acc[nt][0], d * acc[nt][1]);
    }
    if (r0 + 8 < n) {
        float d = g_dis[r0 + 8];
        __half2* p = (__half2*)(g_h + (size_t)(r0 + 8) * FDIM) + cp;
#pragma unroll
        for (int nt = 0; nt < 16; nt++)
            p[nt * 4] = __floats2half2_rn(d * acc[nt][2], d * acc[nt][3]);
    }
}

// ---------------------------------------------------------------------------
// 6) gather: one warp per node. fp16 rows (256 B), fp32 accumulation.
//    out = relu( dis[i] * (h'[i] + sum h'[s]) + b )
__global__ void k_gather(const float* __restrict__ b, float* __restrict__ out, int n) {
    int node = (blockIdx.x * blockDim.x + threadIdx.x) >> 5;
    int lane = threadIdx.x & 31;
    if (node >= n) return;

    const uint2* __restrict__ h2 = (const uint2*)g_h;   // 4 halves per uint2, 32 per row

    float di  = g_dis[node];
    int   s0  = g_start[node];
    int   deg = g_deg[node];

    // self-loop
    uint2 raw = h2[(size_t)node * 32 + lane];
    float2 f0 = __half22float2(*reinterpret_cast<const __half2*>(&raw.x));
    float2 f1 = __half22float2(*reinterpret_cast<const __half2*>(&raw.y));
    float4 acc = make_float4(f0.x, f0.y, f1.x, f1.y);

    for (int base = 0; base < deg; base += 32) {
        int m = deg - base;
        if (m > 32) m = 32;
        int s = (lane < m) ? g_csr[s0 + base + lane] : 0;   // coalesced
#pragma unroll 4
        for (int j = 0; j < m; j++) {
            int sj = __shfl_sync(0xffffffffu, s, j);
            uint2 hv = h2[(size_t)sj * 32 + lane];          // 256 B/row, L2-resident
            float2 a0 = __half22float2(*reinterpret_cast<const __half2*>(&hv.x));
            float2 a1 = __half22float2(*reinterpret_cast<const __half2*>(&hv.y));
            acc.x += a0.x; acc.y += a0.y; acc.z += a1.x; acc.w += a1.y;
        }
    }

    float4 bb = ((const float4*)b)[lane];
    float4 o;
    o.x = fmaxf(fmaf(di, acc.x, bb.x), 0.f);
    o.y = fmaxf(fmaf(di, acc.y, bb.y), 0.f);
    o.z = fmaxf(fmaf(di, acc.z, bb.z), 0.f);
    o.w = fmaxf(fmaf(di, acc.w, bb.w), 0.f);
    ((float4*)out)[(size_t)node * 32 + lane] = o;
}

// ---------------------------------------------------------------------------
extern "C" void kernel_launch(void* const* d_in, const int* in_sizes, int n_in,
                              void* d_out, int out_size) {
    const float* x   = (const float*)d_in[0];
    const void*  ei  = d_in[1];            // [2, E] int32 or int64 (probed)
    const float* W   = (const float*)d_in[2];
    const float* b   = (const float*)d_in[3];
    float*       out = (float*)d_out;

    const int n = in_sizes[0] / FDIM;      // 100000
    const int e = in_sizes[1] / 2;         // 3200000

    // CSR build + normalization (dis needed by GEMM epilogue)
    k_init<<<(n + 255) / 256, 256>>>(ei, n);
    k_deg<<<(e + 255) / 256, 256>>>(ei, e, n);
    k_reserve<<<(n + 255) / 256, 256>>>(n);
    k_fill<<<(e + 255) / 256, 256>>>(ei, e, n);

    // h' = fp16( dis .* (x @ W) )   (tf32 tensor-core GEMM, 128 KB dynamic smem)
    static const int smem = 128 * 1024;
    cudaFuncSetAttribute(k_gemm_tf32, cudaFuncAttributeMaxDynamicSharedMemorySize, smem);
    k_gemm_tf32<<<(n + 127) / 128, 256, smem>>>(x, W, n);

    // fused gather + self-loop + bias + relu (one warp per node)
    long long threads_total = (long long)n * 32;
    k_gather<<<(int)((threads_total + 255) / 256), 256>>>(b, out, n);
}

// round 8
// speedup vs baseline: 1.4232x; 1.0536x over previous
#include <cuda_runtime.h>
#include <cuda_fp16.h>
#include <cstdint>

#define MAXN 100000
#define MAXE 3200000
#define FDIM 128   // IN == OUT == 128

// Scratch (device globals: allocation-free per harness rules)
__device__ __half g_h[(size_t)MAXN * FDIM];  // h' = dis .* (x @ W)  (25.6 MB, fp16)
__device__ float  g_dis[MAXN];               // rsqrt(deg_in + 1)
__device__ int    g_deg[MAXN];               // incoming-edge count (excl. self-loop)
__device__ int    g_start[MAXN];             // CSR bin start
__device__ int    g_cur[MAXN];               // fill cursor
__device__ int    g_csr[MAXE];               // src index per binned edge
__device__ int    g_cursor;                  // global reservation cursor
__device__ int    g_is32;                    // 1 if edge_index is int32, 0 if int64

// ---------------------------------------------------------------------------
// 1) reset degree + dtype probe (fused)
__global__ void k_init(const void* __restrict__ ei, int n) {
    int i = blockIdx.x * blockDim.x + threadIdx.x;
    if (i < n) g_deg[i] = 0;
    if (i == 0) {
        const long long* p = (const long long*)ei;
        int is32 = 0;
        for (int k = 0; k < 64; k++) {
            long long v = p[k];
            if (v < 0 || v >= (long long)n) { is32 = 1; break; }
        }
        g_is32 = is32;
        g_cursor = 0;
    }
}

__device__ __forceinline__ int load_idx(const void* p, long long idx, int is32) {
    if (is32) return ((const int*)p)[idx];
    return (int)((const long long*)p)[idx];
}

// 2) histogram over dst — 4 edges per thread, int4 fast path
__global__ void k_deg(const void* __restrict__ ei, int e, int n) {
    int i = blockIdx.x * blockDim.x + threadIdx.x;
    int base = i * 4;
    if (base >= e) return;
    int is32 = g_is32;
    if (is32 && ((e & 3) == 0) && base + 4 <= e) {
        int4 d4 = ((const int4*)((const int*)ei + e))[i];
        if ((unsigned)d4.x < (unsigned)n) atomicAdd(&g_deg[d4.x], 1);
        if ((unsigned)d4.y < (unsigned)n) atomicAdd(&g_deg[d4.y], 1);
        if ((unsigned)d4.z < (unsigned)n) atomicAdd(&g_deg[d4.z], 1);
        if ((unsigned)d4.w < (unsigned)n) atomicAdd(&g_deg[d4.w], 1);
    } else {
        int hi = base + 4 < e ? base + 4 : e;
        for (int k = base; k < hi; k++) {
            int d = load_idx(ei, (long long)e + k, is32);
            if ((unsigned)d < (unsigned)n) atomicAdd(&g_deg[d], 1);
        }
    }
}

// 3) reserve CSR bins + dis = rsqrt(deg + 1)
__global__ void k_reserve(int n) {
    int i = blockIdx.x * blockDim.x + threadIdx.x;
    if (i < n) {
        int d = g_deg[i];
        int st = atomicAdd(&g_cursor, d);
        g_start[i] = st;
        g_cur[i]   = st;
        g_dis[i]   = rsqrtf((float)(d + 1));
    }
}

// 4) fill CSR — 4 edges per thread, int4 fast path
__global__ void k_fill(const void* __restrict__ ei, int e, int n) {
    int i = blockIdx.x * blockDim.x + threadIdx.x;
    int base = i * 4;
    if (base >= e) return;
    int is32 = g_is32;
    if (is32 && ((e & 3) == 0) && base + 4 <= e) {
        int4 s4 = ((const int4*)((const int*)ei))[i];
        int4 d4 = ((const int4*)((const int*)ei + e))[i];
        if ((unsigned)d4.x < (unsigned)n && (unsigned)s4.x < (unsigned)n)
            g_csr[atomicAdd(&g_cur[d4.x], 1)] = s4.x;
        if ((unsigned)d4.y < (unsigned)n && (unsigned)s4.y < (unsigned)n)
            g_csr[atomicAdd(&g_cur[d4.y], 1)] = s4.y;
        if ((unsigned)d4.z < (unsigned)n && (unsigned)s4.z < (unsigned)n)
            g_csr[atomicAdd(&g_cur[d4.z], 1)] = s4.z;
        if ((unsigned)d4.w < (unsigned)n && (unsigned)s4.w < (unsigned)n)
            g_csr[atomicAdd(&g_cur[d4.w], 1)] = s4.w;
    } else {
        int hi = base + 4 < e ? base + 4 : e;
        for (int k = base; k < hi; k++) {
            int s = load_idx(ei, k, is32);
            int d = load_idx(ei, (long long)e + k, is32);
            if ((unsigned)d < (unsigned)n && (unsigned)s < (unsigned)n)
                g_csr[atomicAdd(&g_cur[d], 1)] = s;
        }
    }
}

// ---------------------------------------------------------------------------
// 5) GEMM via tf32 mma.sync (m16n8k8), 128x128x128 per block, 256 threads.
//    Epilogue: g_h[r] = fp16( dis[r] * (x@W)[r] ).  Runs concurrently with k_fill.
__global__ void k_gemm_tf32(const float* __restrict__ x, const float* __restrict__ W, int n) {
    extern __shared__ uint32_t sm[];
    uint32_t* A = sm;            // [16 ks][8 w][32 lane][4 reg]   = 64 KB
    uint32_t* B = sm + 16384;    // [16 ks][16 nt][32 lane][2 reg] = 64 KB

    const int row0 = blockIdx.x * 128;
    const int tid  = threadIdx.x;

    for (int i = tid; i < 16 * 8 * 32; i += 256) {
        int lane = i & 31;
        int w    = (i >> 5) & 7;
        int ks   = i >> 8;
        int r    = row0 + w * 16 + (lane >> 2);
        int c    = ks * 8 + (lane & 3);
        float v0 = 0.f, v1 = 0.f, v2 = 0.f, v3 = 0.f;
        if (r < n)     { v0 = x[(size_t)r * FDIM + c];       v2 = x[(size_t)r * FDIM + c + 4]; }
        if (r + 8 < n) { v1 = x[(size_t)(r + 8) * FDIM + c]; v3 = x[(size_t)(r + 8) * FDIM + c + 4]; }
        uint32_t t0, t1, t2, t3;
        asm("cvt.rna.tf32.f32 %0, %1;" : "=r"(t0) : "f"(v0));
        asm("cvt.rna.tf32.f32 %0, %1;" : "=r"(t1) : "f"(v1));
        asm("cvt.rna.tf32.f32 %0, %1;" : "=r"(t2) : "f"(v2));
        asm("cvt.rna.tf32.f32 %0, %1;" : "=r"(t3) : "f"(v3));
        *(uint4*)&A[(size_t)i * 4] = make_uint4(t0, t1, t2, t3);
    }

    for (int i = tid; i < 16 * 16 * 32; i += 256) {
        int lane = i & 31;
        int nt   = (i >> 5) & 15;
        int ks   = i >> 9;
        int k    = ks * 8 + (lane & 3);
        int c    = nt * 8 + (lane >> 2);
        float v0 = W[(size_t)k * FDIM + c];
        float v1 = W[(size_t)(k + 4) * FDIM + c];
        uint32_t t0, t1;
        asm("cvt.rna.tf32.f32 %0, %1;" : "=r"(t0) : "f"(v0));
        asm("cvt.rna.tf32.f32 %0, %1;" : "=r"(t1) : "f"(v1));
        *(uint2*)&B[(size_t)i * 2] = make_uint2(t0, t1);
    }
    __syncthreads();

    const int lane = tid & 31;
    const int w    = tid >> 5;

    float acc[16][4];
#pragma unroll
    for (int nt = 0; nt < 16; nt++) { acc[nt][0] = acc[nt][1] = acc[nt][2] = acc[nt][3] = 0.f; }

#pragma unroll
    for (int ks = 0; ks < 16; ks++) {
        uint4 a = *(const uint4*)&A[(((ks * 8 + w) * 32 + lane)) * 4];
#pragma unroll
        for (int nt = 0; nt < 16; nt++) {
            uint2 b = *(const uint2*)&B[(((ks * 16 + nt) * 32 + lane)) * 2];
            asm volatile(
                "mma.sync.aligned.m16n8k8.row.col.f32.tf32.tf32.f32 "
                "{%0,%1,%2,%3}, {%4,%5,%6,%7}, {%8,%9}, {%0,%1,%2,%3};"
                : "+f"(acc[nt][0]), "+f"(acc[nt][1]), "+f"(acc[nt][2]), "+f"(acc[nt][3])
                : "r"(a.x), "r"(a.y), "r"(a.z), "r"(a.w), "r"(b.x), "r"(b.y));
        }
    }

    int r0 = row0 + w * 16 + (lane >> 2);
    int cp = lane & 3;
    if (r0 < n) {
        float d = g_dis[r0];
        __half2* p = (__half2*)(g_h + (size_t)r0 * FDIM) + cp;
#pragma unroll
        for (int nt = 0; nt < 16; nt++)
            p[nt * 4] = __floats2half2_rn(d * acc[nt][0], d * acc[nt][1]);
    }
    if (r0 + 8 < n) {
        float d = g_dis[r0 + 8];
        __half2* p = (__half2*)(g_h + (size_t)(r0 + 8) * FDIM) + cp;
#pragma unroll
        for (int nt = 0; nt < 16; nt++)
            p[nt * 4] = __floats2half2_rn(d * acc[nt][2], d * acc[nt][3]);
    }
}

// ---------------------------------------------------------------------------
// 6) gather: one warp per node. fp16 rows (256 B), fp32 accumulation.
__global__ void k_gather(const float* __restrict__ b, float* __restrict__ out, int n) {
    int node = (blockIdx.x * blockDim.x + threadIdx.x) >> 5;
    int lane = threadIdx.x & 31;
    if (node >= n) return;

    const uint2* __restrict__ h2 = (const uint2*)g_h;

    float di  = g_dis[node];
    int   s0  = g_start[node];
    int   deg = g_deg[node];

    uint2 raw = h2[(size_t)node * 32 + lane];
    float2 f0 = __half22float2(*reinterpret_cast<const __half2*>(&raw.x));
    float2 f1 = __half22float2(*reinterpret_cast<const __half2*>(&raw.y));
    float4 acc = make_float4(f0.x, f0.y, f1.x, f1.y);

    for (int base = 0; base < deg; base += 32) {
        int m = deg - base;
        if (m > 32) m = 32;
        int s = (lane < m) ? g_csr[s0 + base + lane] : 0;
#pragma unroll 4
        for (int j = 0; j < m; j++) {
            int sj = __shfl_sync(0xffffffffu, s, j);
            uint2 hv = h2[(size_t)sj * 32 + lane];
            float2 a0 = __half22float2(*reinterpret_cast<const __half2*>(&hv.x));
            float2 a1 = __half22float2(*reinterpret_cast<const __half2*>(&hv.y));
            acc.x += a0.x; acc.y += a0.y; acc.z += a1.x; acc.w += a1.y;
        }
    }

    float4 bb = ((const float4*)b)[lane];
    float4 o;
    o.x = fmaxf(fmaf(di, acc.x, bb.x), 0.f);
    o.y = fmaxf(fmaf(di, acc.y, bb.y), 0.f);
    o.z = fmaxf(fmaf(di, acc.z, bb.z), 0.f);
    o.w = fmaxf(fmaf(di, acc.w, bb.w), 0.f);
    ((float4*)out)[(size_t)node * 32 + lane] = o;
}

// ---------------------------------------------------------------------------
extern "C" void kernel_launch(void* const* d_in, const int* in_sizes, int n_in,
                              void* d_out, int out_size) {
    const float* x   = (const float*)d_in[0];
    const void*  ei  = d_in[1];            // [2, E] int32 or int64 (probed)
    const float* W   = (const float*)d_in[2];
    const float* b   = (const float*)d_in[3];
    float*       out = (float*)d_out;

    const int n = in_sizes[0] / FDIM;      // 100000
    const int e = in_sizes[1] / 2;         // 3200000

    // Side stream + events, created once on the first (uncaptured) call.
    static cudaStream_t s1 = nullptr;
    static cudaEvent_t  ev_fork = nullptr, ev_gemm = nullptr;
    if (s1 == nullptr) {
        cudaStreamCreateWithFlags(&s1, cudaStreamNonBlocking);
        cudaEventCreateWithFlags(&ev_fork, cudaEventDisableTiming);
        cudaEventCreateWithFlags(&ev_gemm, cudaEventDisableTiming);
        cudaFuncSetAttribute(k_gemm_tf32, cudaFuncAttributeMaxDynamicSharedMemorySize,
                             128 * 1024);
    }

    // CSR chain head (capture stream): probe+init -> deg -> reserve (dis ready)
    k_init<<<(n + 255) / 256, 256>>>(ei, n);
    int edge_threads = (e + 3) / 4;
    k_deg<<<(edge_threads + 255) / 256, 256>>>(ei, e, n);
    k_reserve<<<(n + 255) / 256, 256>>>(n);

    // Fork: GEMM (needs g_dis only) on s1, concurrent with k_fill on capture stream
    cudaEventRecord(ev_fork, 0);
    cudaStreamWaitEvent(s1, ev_fork, 0);
    k_gemm_tf32<<<(n + 127) / 128, 256, 128 * 1024, s1>>>(x, W, n);
    cudaEventRecord(ev_gemm, s1);

    k_fill<<<(edge_threads + 255) / 256, 256>>>(ei, e, n);

    // Join: gather needs both CSR (capture stream) and g_h (s1)
    cudaStreamWaitEvent(0, ev_gemm, 0);
    long long threads_total = (long long)n * 32;
    k_gather<<<(int)((threads_total + 255) / 256), 256>>>(b, out, n);
}

// round 9
// speedup vs baseline: 1.5376x; 1.0803x over previous
#include <cuda_runtime.h>
#include <cuda_fp16.h>
#include <cstdint>

#define MAXN 100000
#define MAXE 3200000
#define FDIM 128   // IN == OUT == 128

// Scratch (device globals: allocation-free per harness rules)
__device__ float    g_hraw[(size_t)MAXN * FDIM]; // x @ W, fp32 raw  (51.2 MB)
__device__ __half   g_h[(size_t)MAXN * FDIM];    // dis .* (x@W), fp16 (25.6 MB)
__device__ uint32_t g_Wfrag[16384];              // W in tf32 fragment layout (64 KB)
__device__ float    g_dis[MAXN];                 // rsqrt(deg_in + 1)
__device__ int      g_deg[MAXN];
__device__ int      g_start[MAXN];
__device__ int      g_cur[MAXN];
__device__ int      g_csr[MAXE];
__device__ int      g_cursor;
__device__ int      g_is32;

// ---------------------------------------------------------------------------
// 1) reset degree + dtype probe (fused)
__global__ void k_init(const void* __restrict__ ei, int n) {
    int i = blockIdx.x * blockDim.x + threadIdx.x;
    if (i < n) g_deg[i] = 0;
    if (i == 0) {
        const long long* p = (const long long*)ei;
        int is32 = 0;
        for (int k = 0; k < 64; k++) {
            long long v = p[k];
            if (v < 0 || v >= (long long)n) { is32 = 1; break; }
        }
        g_is32 = is32;
        g_cursor = 0;
    }
}

__device__ __forceinline__ int load_idx(const void* p, long long idx, int is32) {
    if (is32) return ((const int*)p)[idx];
    return (int)((const long long*)p)[idx];
}

// 2) histogram over dst — 4 edges per thread, int4 fast path
__global__ void k_deg(const void* __restrict__ ei, int e, int n) {
    int i = blockIdx.x * blockDim.x + threadIdx.x;
    int base = i * 4;
    if (base >= e) return;
    int is32 = g_is32;
    if (is32 && ((e & 3) == 0) && base + 4 <= e) {
        int4 d4 = ((const int4*)((const int*)ei + e))[i];
        if ((unsigned)d4.x < (unsigned)n) atomicAdd(&g_deg[d4.x], 1);
        if ((unsigned)d4.y < (unsigned)n) atomicAdd(&g_deg[d4.y], 1);
        if ((unsigned)d4.z < (unsigned)n) atomicAdd(&g_deg[d4.z], 1);
        if ((unsigned)d4.w < (unsigned)n) atomicAdd(&g_deg[d4.w], 1);
    } else {
        int hi = base + 4 < e ? base + 4 : e;
        for (int k = base; k < hi; k++) {
            int d = load_idx(ei, (long long)e + k, is32);
            if ((unsigned)d < (unsigned)n) atomicAdd(&g_deg[d], 1);
        }
    }
}

// 3) reserve CSR bins + dis = rsqrt(deg + 1)
__global__ void k_reserve(int n) {
    int i = blockIdx.x * blockDim.x + threadIdx.x;
    if (i < n) {
        int d = g_deg[i];
        int st = atomicAdd(&g_cursor, d);
        g_start[i] = st;
        g_cur[i]   = st;
        g_dis[i]   = rsqrtf((float)(d + 1));
    }
}

// 4) fill CSR — 4 edges per thread, int4 fast path
__global__ void k_fill(const void* __restrict__ ei, int e, int n) {
    int i = blockIdx.x * blockDim.x + threadIdx.x;
    int base = i * 4;
    if (base >= e) return;
    int is32 = g_is32;
    if (is32 && ((e & 3) == 0) && base + 4 <= e) {
        int4 s4 = ((const int4*)((const int*)ei))[i];
        int4 d4 = ((const int4*)((const int*)ei + e))[i];
        if ((unsigned)d4.x < (unsigned)n && (unsigned)s4.x < (unsigned)n)
            g_csr[atomicAdd(&g_cur[d4.x], 1)] = s4.x;
        if ((unsigned)d4.y < (unsigned)n && (unsigned)s4.y < (unsigned)n)
            g_csr[atomicAdd(&g_cur[d4.y], 1)] = s4.y;
        if ((unsigned)d4.z < (unsigned)n && (unsigned)s4.z < (unsigned)n)
            g_csr[atomicAdd(&g_cur[d4.z], 1)] = s4.z;
        if ((unsigned)d4.w < (unsigned)n && (unsigned)s4.w < (unsigned)n)
            g_csr[atomicAdd(&g_cur[d4.w], 1)] = s4.w;
    } else {
        int hi = base + 4 < e ? base + 4 : e;
        for (int k = base; k < hi; k++) {
            int s = load_idx(ei, k, is32);
            int d = load_idx(ei, (long long)e + k, is32);
            if ((unsigned)d < (unsigned)n && (unsigned)s < (unsigned)n)
                g_csr[atomicAdd(&g_cur[d], 1)] = s;
        }
    }
}

// ---------------------------------------------------------------------------
// 5a) pre-swizzle W into tf32 m16n8k8 B-fragment layout (global, 64 KB)
//     entry (ks, nt, lane): b0 = W[ks*8 + (lane&3)][nt*8 + (lane>>2)], b1 = +4 row
__global__ void k_wprep(const float* __restrict__ W) {
    int i = blockIdx.x * blockDim.x + threadIdx.x;   // 8192 entries
    if (i >= 8192) return;
    int lane = i & 31;
    int nt   = (i >> 5) & 15;
    int ks   = i >> 9;
    int k    = ks * 8 + (lane & 3);
    int c    = nt * 8 + (lane >> 2);
    uint32_t t0, t1;
    asm("cvt.rna.tf32.f32 %0, %1;" : "=r"(t0) : "f"(W[(size_t)k * FDIM + c]));
    asm("cvt.rna.tf32.f32 %0, %1;" : "=r"(t1) : "f"(W[(size_t)(k + 4) * FDIM + c]));
    *(uint2*)&g_Wfrag[(size_t)i * 2] = make_uint2(t0, t1);
}

// 5b) GEMM: g_hraw = x @ W (raw, no dis). A staged in 64 KB smem (fragment
//     layout); B fragments via coalesced L1-resident LDG from g_Wfrag.
//     2 CTAs/SM (64 KB smem, <=128 regs).
__global__ void __launch_bounds__(256, 2)
k_gemm_tf32(const float* __restrict__ x, int n) {
    extern __shared__ uint32_t sm[];
    uint32_t* A = sm;            // [16 ks][8 w][32 lane][4 reg] = 64 KB

    const int row0 = blockIdx.x * 128;
    const int tid  = threadIdx.x;

    for (int i = tid; i < 16 * 8 * 32; i += 256) {
        int lane = i & 31;
        int w    = (i >> 5) & 7;
        int ks   = i >> 8;
        int r    = row0 + w * 16 + (lane >> 2);
        int c    = ks * 8 + (lane & 3);
        float v0 = 0.f, v1 = 0.f, v2 = 0.f, v3 = 0.f;
        if (r < n)     { v0 = x[(size_t)r * FDIM + c];       v2 = x[(size_t)r * FDIM + c + 4]; }
        if (r + 8 < n) { v1 = x[(size_t)(r + 8) * FDIM + c]; v3 = x[(size_t)(r + 8) * FDIM + c + 4]; }
        uint32_t t0, t1, t2, t3;
        asm("cvt.rna.tf32.f32 %0, %1;" : "=r"(t0) : "f"(v0));
        asm("cvt.rna.tf32.f32 %0, %1;" : "=r"(t1) : "f"(v1));
        asm("cvt.rna.tf32.f32 %0, %1;" : "=r"(t2) : "f"(v2));
        asm("cvt.rna.tf32.f32 %0, %1;" : "=r"(t3) : "f"(v3));
        *(uint4*)&A[(size_t)i * 4] = make_uint4(t0, t1, t2, t3);
    }
    __syncthreads();

    const int lane = tid & 31;
    const int w    = tid >> 5;

    float acc[16][4];
#pragma unroll
    for (int nt = 0; nt < 16; nt++) { acc[nt][0] = acc[nt][1] = acc[nt][2] = acc[nt][3] = 0.f; }

    const uint2* __restrict__ Bf = (const uint2*)g_Wfrag;

#pragma unroll
    for (int ks = 0; ks < 16; ks++) {
        uint4 a = *(const uint4*)&A[(((ks * 8 + w) * 32 + lane)) * 4];
#pragma unroll
        for (int nt = 0; nt < 16; nt++) {
            uint2 b = __ldg(&Bf[(ks * 16 + nt) * 32 + lane]);   // coalesced, L1-hot
            asm volatile(
                "mma.sync.aligned.m16n8k8.row.col.f32.tf32.tf32.f32 "
                "{%0,%1,%2,%3}, {%4,%5,%6,%7}, {%8,%9}, {%0,%1,%2,%3};"
                : "+f"(acc[nt][0]), "+f"(acc[nt][1]), "+f"(acc[nt][2]), "+f"(acc[nt][3])
                : "r"(a.x), "r"(a.y), "r"(a.z), "r"(a.w), "r"(b.x), "r"(b.y));
        }
    }

    // epilogue: write fp32 raw (c0,c1 adjacent cols -> float2)
    int r0 = row0 + w * 16 + (lane >> 2);
    int cb = 2 * (lane & 3);
    if (r0 < n) {
        float* p = g_hraw + (size_t)r0 * FDIM + cb;
#pragma unroll
        for (int nt = 0; nt < 16; nt++)
            *(float2*)(p + nt * 8) = make_float2(acc[nt][0], acc[nt][1]);
    }
    if (r0 + 8 < n) {
        float* p = g_hraw + (size_t)(r0 + 8) * FDIM + cb;
#pragma unroll
        for (int nt = 0; nt < 16; nt++)
            *(float2*)(p + nt * 8) = make_float2(acc[nt][2], acc[nt][3]);
    }
}

// 5c) scale: g_h = fp16( dis[row] * g_hraw ).  8 floats per thread.
__global__ void k_scale(int n) {
    int i = blockIdx.x * blockDim.x + threadIdx.x;   // n*16 threads
    if (i >= n * 16) return;
    int node = i >> 4;
    float d = g_dis[node];
    const float4* src = (const float4*)g_hraw + (size_t)i * 2;
    float4 v0 = src[0], v1 = src[1];
    __half2 h0 = __floats2half2_rn(d * v0.x, d * v0.y);
    __half2 h1 = __floats2half2_rn(d * v0.z, d * v0.w);
    __half2 h2 = __floats2half2_rn(d * v1.x, d * v1.y);
    __half2 h3 = __floats2half2_rn(d * v1.z, d * v1.w);
    uint2* dst = (uint2*)g_h + (size_t)i * 2;
    dst[0] = make_uint2(*(uint32_t*)&h0, *(uint32_t*)&h1);
    dst[1] = make_uint2(*(uint32_t*)&h2, *(uint32_t*)&h3);
}

// ---------------------------------------------------------------------------
// 6) gather: one warp per node. fp16 rows (256 B), fp32 accumulation.
__global__ void k_gather(const float* __restrict__ b, float* __restrict__ out, int n) {
    int node = (blockIdx.x * blockDim.x + threadIdx.x) >> 5;
    int lane = threadIdx.x & 31;
    if (node >= n) return;

    const uint2* __restrict__ h2 = (const uint2*)g_h;

    float di  = g_dis[node];
    int   s0  = g_start[node];
    int   deg = g_deg[node];

    uint2 raw = h2[(size_t)node * 32 + lane];
    float2 f0 = __half22float2(*reinterpret_cast<const __half2*>(&raw.x));
    float2 f1 = __half22float2(*reinterpret_cast<const __half2*>(&raw.y));
    float4 acc = make_float4(f0.x, f0.y, f1.x, f1.y);

    for (int base = 0; base < deg; base += 32) {
        int m = deg - base;
        if (m > 32) m = 32;
        int s = (lane < m) ? g_csr[s0 + base + lane] : 0;
#pragma unroll 4
        for (int j = 0; j < m; j++) {
            int sj = __shfl_sync(0xffffffffu, s, j);
            uint2 hv = h2[(size_t)sj * 32 + lane];
            float2 a0 = __half22float2(*reinterpret_cast<const __half2*>(&hv.x));
            float2 a1 = __half22float2(*reinterpret_cast<const __half2*>(&hv.y));
            acc.x += a0.x; acc.y += a0.y; acc.z += a1.x; acc.w += a1.y;
        }
    }

    float4 bb = ((const float4*)b)[lane];
    float4 o;
    o.x = fmaxf(fmaf(di, acc.x, bb.x), 0.f);
    o.y = fmaxf(fmaf(di, acc.y, bb.y), 0.f);
    o.z = fmaxf(fmaf(di, acc.z, bb.z), 0.f);
    o.w = fmaxf(fmaf(di, acc.w, bb.w), 0.f);
    ((float4*)out)[(size_t)node * 32 + lane] = o;
}

// ---------------------------------------------------------------------------
extern "C" void kernel_launch(void* const* d_in, const int* in_sizes, int n_in,
                              void* d_out, int out_size) {
    const float* x   = (const float*)d_in[0];
    const void*  ei  = d_in[1];            // [2, E] int32 or int64 (probed)
    const float* W   = (const float*)d_in[2];
    const float* b   = (const float*)d_in[3];
    float*       out = (float*)d_out;

    const int n = in_sizes[0] / FDIM;      // 100000
    const int e = in_sizes[1] / 2;         // 3200000

    static cudaStream_t s1 = nullptr;
    static cudaEvent_t  ev_fork = nullptr, ev_res = nullptr, ev_scale = nullptr;
    if (s1 == nullptr) {
        cudaStreamCreateWithFlags(&s1, cudaStreamNonBlocking);
        cudaEventCreateWithFlags(&ev_fork,  cudaEventDisableTiming);
        cudaEventCreateWithFlags(&ev_res,   cudaEventDisableTiming);
        cudaEventCreateWithFlags(&ev_scale, cudaEventDisableTiming);
        cudaFuncSetAttribute(k_gemm_tf32, cudaFuncAttributeMaxDynamicSharedMemorySize,
                             64 * 1024);
    }

    // Fork at t=0: GEMM chain (no CSR dependencies) on s1
    cudaEventRecord(ev_fork, 0);
    cudaStreamWaitEvent(s1, ev_fork, 0);
    k_wprep<<<32, 256, 0, s1>>>(W);
    k_gemm_tf32<<<(n + 127) / 128, 256, 64 * 1024, s1>>>(x, n);

    // CSR chain on capture stream
    k_init<<<(n + 255) / 256, 256>>>(ei, n);
    int edge_threads = (e + 3) / 4;
    k_deg<<<(edge_threads + 255) / 256, 256>>>(ei, e, n);
    k_reserve<<<(n + 255) / 256, 256>>>(n);
    cudaEventRecord(ev_res, 0);

    // scale needs gemm (in-stream on s1) + reserve (event)
    cudaStreamWaitEvent(s1, ev_res, 0);
    int st = n * 16;
    k_scale<<<(st + 255) / 256, 256, 0, s1>>>(n);
    cudaEventRecord(ev_scale, s1);

    // fill runs concurrent with gemm/scale
    k_fill<<<(edge_threads + 255) / 256, 256>>>(ei, e, n);

    // join: gather needs CSR (in-stream) + g_h (event)
    cudaStreamWaitEvent(0, ev_scale, 0);
    long long threads_total = (long long)n * 32;
    k_gather<<<(int)((threads_total + 255) / 256), 256>>>(b, out, n);
}

// round 10
// speedup vs baseline: 1.5892x; 1.0335x over previous
#include <cuda_runtime.h>
#include <cuda_fp16.h>
#include <cstdint>

#define MAXN 100000
#define MAXE 3200000
#define FDIM 128   // IN == OUT == 128

// Scratch (device globals: allocation-free per harness rules)
__device__ float    g_hraw[(size_t)MAXN * FDIM]; // x @ W, fp32 raw  (51.2 MB)
__device__ __half   g_h[(size_t)MAXN * FDIM];    // dis .* (x@W), fp16 (25.6 MB)
__device__ uint32_t g_Wfrag[16384];              // W in tf32 fragment layout (64 KB)
__device__ float    g_dis[MAXN];                 // rsqrt(deg_in + 1)
__device__ int      g_deg[MAXN];
__device__ int      g_start[MAXN];
__device__ int      g_cur[MAXN];
__device__ int      g_csr[MAXE];
__device__ int      g_cursor;
__device__ int      g_is32;

// ---------------------------------------------------------------------------
// 1) reset degree + dtype probe (fused)
__global__ void k_init(const void* __restrict__ ei, int n) {
    int i = blockIdx.x * blockDim.x + threadIdx.x;
    if (i < n) g_deg[i] = 0;
    if (i == 0) {
        const long long* p = (const long long*)ei;
        int is32 = 0;
        for (int k = 0; k < 64; k++) {
            long long v = p[k];
            if (v < 0 || v >= (long long)n) { is32 = 1; break; }
        }
        g_is32 = is32;
        g_cursor = 0;
    }
}

__device__ __forceinline__ int load_idx(const void* p, long long idx, int is32) {
    if (is32) return ((const int*)p)[idx];
    return (int)((const long long*)p)[idx];
}

// 2) histogram over dst — 8 edges per thread (2x int4) for load/atomic MLP
__global__ void k_deg(const void* __restrict__ ei, int e, int n) {
    int i = blockIdx.x * blockDim.x + threadIdx.x;
    int base = i * 8;
    if (base >= e) return;
    int is32 = g_is32;
    if (is32 && ((e & 7) == 0) && base + 8 <= e) {
        const int4* dp = (const int4*)((const int*)ei + e);
        int4 a = dp[i * 2];
        int4 c = dp[i * 2 + 1];
        if ((unsigned)a.x < (unsigned)n) atomicAdd(&g_deg[a.x], 1);
        if ((unsigned)a.y < (unsigned)n) atomicAdd(&g_deg[a.y], 1);
        if ((unsigned)a.z < (unsigned)n) atomicAdd(&g_deg[a.z], 1);
        if ((unsigned)a.w < (unsigned)n) atomicAdd(&g_deg[a.w], 1);
        if ((unsigned)c.x < (unsigned)n) atomicAdd(&g_deg[c.x], 1);
        if ((unsigned)c.y < (unsigned)n) atomicAdd(&g_deg[c.y], 1);
        if ((unsigned)c.z < (unsigned)n) atomicAdd(&g_deg[c.z], 1);
        if ((unsigned)c.w < (unsigned)n) atomicAdd(&g_deg[c.w], 1);
    } else {
        int hi = base + 8 < e ? base + 8 : e;
        for (int k = base; k < hi; k++) {
            int d = load_idx(ei, (long long)e + k, is32);
            if ((unsigned)d < (unsigned)n) atomicAdd(&g_deg[d], 1);
        }
    }
}

// 3) reserve CSR bins + dis = rsqrt(deg + 1)
__global__ void k_reserve(int n) {
    int i = blockIdx.x * blockDim.x + threadIdx.x;
    if (i < n) {
        int d = g_deg[i];
        int st = atomicAdd(&g_cursor, d);
        g_start[i] = st;
        g_cur[i]   = st;
        g_dis[i]   = rsqrtf((float)(d + 1));
    }
}

// 4) fill CSR — 4 edges per thread, int4 fast path
__global__ void k_fill(const void* __restrict__ ei, int e, int n) {
    int i = blockIdx.x * blockDim.x + threadIdx.x;
    int base = i * 4;
    if (base >= e) return;
    int is32 = g_is32;
    if (is32 && ((e & 3) == 0) && base + 4 <= e) {
        int4 s4 = ((const int4*)((const int*)ei))[i];
        int4 d4 = ((const int4*)((const int*)ei + e))[i];
        if ((unsigned)d4.x < (unsigned)n && (unsigned)s4.x < (unsigned)n)
            g_csr[atomicAdd(&g_cur[d4.x], 1)] = s4.x;
        if ((unsigned)d4.y < (unsigned)n && (unsigned)s4.y < (unsigned)n)
            g_csr[atomicAdd(&g_cur[d4.y], 1)] = s4.y;
        if ((unsigned)d4.z < (unsigned)n && (unsigned)s4.z < (unsigned)n)
            g_csr[atomicAdd(&g_cur[d4.z], 1)] = s4.z;
        if ((unsigned)d4.w < (unsigned)n && (unsigned)s4.w < (unsigned)n)
            g_csr[atomicAdd(&g_cur[d4.w], 1)] = s4.w;
    } else {
        int hi = base + 4 < e ? base + 4 : e;
        for (int k = base; k < hi; k++) {
            int s = load_idx(ei, k, is32);
            int d = load_idx(ei, (long long)e + k, is32);
            if ((unsigned)d < (unsigned)n && (unsigned)s < (unsigned)n)
                g_csr[atomicAdd(&g_cur[d], 1)] = s;
        }
    }
}

// ---------------------------------------------------------------------------
// 5a) pre-swizzle W into tf32 m16n8k8 B-fragment layout (global, 64 KB)
__global__ void k_wprep(const float* __restrict__ W) {
    int i = blockIdx.x * blockDim.x + threadIdx.x;   // 8192 entries
    if (i >= 8192) return;
    int lane = i & 31;
    int nt   = (i >> 5) & 15;
    int ks   = i >> 9;
    int k    = ks * 8 + (lane & 3);
    int c    = nt * 8 + (lane >> 2);
    uint32_t t0, t1;
    asm("cvt.rna.tf32.f32 %0, %1;" : "=r"(t0) : "f"(W[(size_t)k * FDIM + c]));
    asm("cvt.rna.tf32.f32 %0, %1;" : "=r"(t1) : "f"(W[(size_t)(k + 4) * FDIM + c]));
    *(uint2*)&g_Wfrag[(size_t)i * 2] = make_uint2(t0, t1);
}

// 5b) GEMM: g_hraw = x @ W (raw). A staged in 64 KB smem; B via L1-hot LDG.
__global__ void __launch_bounds__(256, 2)
k_gemm_tf32(const float* __restrict__ x, int n) {
    extern __shared__ uint32_t sm[];
    uint32_t* A = sm;            // [16 ks][8 w][32 lane][4 reg] = 64 KB

    const int row0 = blockIdx.x * 128;
    const int tid  = threadIdx.x;

    for (int i = tid; i < 16 * 8 * 32; i += 256) {
        int lane = i & 31;
        int w    = (i >> 5) & 7;
        int ks   = i >> 8;
        int r    = row0 + w * 16 + (lane >> 2);
        int c    = ks * 8 + (lane & 3);
        float v0 = 0.f, v1 = 0.f, v2 = 0.f, v3 = 0.f;
        if (r < n)     { v0 = x[(size_t)r * FDIM + c];       v2 = x[(size_t)r * FDIM + c + 4]; }
        if (r + 8 < n) { v1 = x[(size_t)(r + 8) * FDIM + c]; v3 = x[(size_t)(r + 8) * FDIM + c + 4]; }
        uint32_t t0, t1, t2, t3;
        asm("cvt.rna.tf32.f32 %0, %1;" : "=r"(t0) : "f"(v0));
        asm("cvt.rna.tf32.f32 %0, %1;" : "=r"(t1) : "f"(v1));
        asm("cvt.rna.tf32.f32 %0, %1;" : "=r"(t2) : "f"(v2));
        asm("cvt.rna.tf32.f32 %0, %1;" : "=r"(t3) : "f"(v3));
        *(uint4*)&A[(size_t)i * 4] = make_uint4(t0, t1, t2, t3);
    }
    __syncthreads();

    const int lane = tid & 31;
    const int w    = tid >> 5;

    float acc[16][4];
#pragma unroll
    for (int nt = 0; nt < 16; nt++) { acc[nt][0] = acc[nt][1] = acc[nt][2] = acc[nt][3] = 0.f; }

    const uint2* __restrict__ Bf = (const uint2*)g_Wfrag;

#pragma unroll
    for (int ks = 0; ks < 16; ks++) {
        uint4 a = *(const uint4*)&A[(((ks * 8 + w) * 32 + lane)) * 4];
#pragma unroll
        for (int nt = 0; nt < 16; nt++) {
            uint2 b = __ldg(&Bf[(ks * 16 + nt) * 32 + lane]);
            asm volatile(
                "mma.sync.aligned.m16n8k8.row.col.f32.tf32.tf32.f32 "
                "{%0,%1,%2,%3}, {%4,%5,%6,%7}, {%8,%9}, {%0,%1,%2,%3};"
                : "+f"(acc[nt][0]), "+f"(acc[nt][1]), "+f"(acc[nt][2]), "+f"(acc[nt][3])
                : "r"(a.x), "r"(a.y), "r"(a.z), "r"(a.w), "r"(b.x), "r"(b.y));
        }
    }

    int r0 = row0 + w * 16 + (lane >> 2);
    int cb = 2 * (lane & 3);
    if (r0 < n) {
        float* p = g_hraw + (size_t)r0 * FDIM + cb;
#pragma unroll
        for (int nt = 0; nt < 16; nt++)
            *(float2*)(p + nt * 8) = make_float2(acc[nt][0], acc[nt][1]);
    }
    if (r0 + 8 < n) {
        float* p = g_hraw + (size_t)(r0 + 8) * FDIM + cb;
#pragma unroll
        for (int nt = 0; nt < 16; nt++)
            *(float2*)(p + nt * 8) = make_float2(acc[nt][2], acc[nt][3]);
    }
}

// 5c) scale: g_h = fp16( dis[row] * g_hraw )
__global__ void k_scale(int n) {
    int i = blockIdx.x * blockDim.x + threadIdx.x;   // n*16 threads
    if (i >= n * 16) return;
    int node = i >> 4;
    float d = g_dis[node];
    const float4* src = (const float4*)g_hraw + (size_t)i * 2;
    float4 v0 = src[0], v1 = src[1];
    __half2 h0 = __floats2half2_rn(d * v0.x, d * v0.y);
    __half2 h1 = __floats2half2_rn(d * v0.z, d * v0.w);
    __half2 h2 = __floats2half2_rn(d * v1.x, d * v1.y);
    __half2 h3 = __floats2half2_rn(d * v1.z, d * v1.w);
    uint2* dst = (uint2*)g_h + (size_t)i * 2;
    dst[0] = make_uint2(*(uint32_t*)&h0, *(uint32_t*)&h1);
    dst[1] = make_uint2(*(uint32_t*)&h2, *(uint32_t*)&h3);
}

// ---------------------------------------------------------------------------
// 6) gather: one warp per node. Full 32-edge chunks specialize to batches of
//    8 independent row loads (deep MLP); tail handled scalar.
__global__ void k_gather(const float* __restrict__ b, float* __restrict__ out, int n) {
    int node = (blockIdx.x * blockDim.x + threadIdx.x) >> 5;
    int lane = threadIdx.x & 31;
    if (node >= n) return;

    const uint2* __restrict__ h2 = (const uint2*)g_h;

    float di  = g_dis[node];
    int   s0  = g_start[node];
    int   deg = g_deg[node];

    uint2 raw = h2[(size_t)node * 32 + lane];
    float2 f0 = __half22float2(*reinterpret_cast<const __half2*>(&raw.x));
    float2 f1 = __half22float2(*reinterpret_cast<const __half2*>(&raw.y));
    float4 acc = make_float4(f0.x, f0.y, f1.x, f1.y);

    int nfull = deg & ~31;

    // full chunks: 32 coalesced indices, then 4 batches of 8 in-flight loads
    for (int base = 0; base < nfull; base += 32) {
        int s = g_csr[s0 + base + lane];
#pragma unroll
        for (int jj = 0; jj < 32; jj += 8) {
            int sj[8];
#pragma unroll
            for (int t = 0; t < 8; t++) sj[t] = __shfl_sync(0xffffffffu, s, jj + t);
            uint2 v[8];
#pragma unroll
            for (int t = 0; t < 8; t++) v[t] = h2[(size_t)sj[t] * 32 + lane];
#pragma unroll
            for (int t = 0; t < 8; t++) {
                float2 a0 = __half22float2(*reinterpret_cast<const __half2*>(&v[t].x));
                float2 a1 = __half22float2(*reinterpret_cast<const __half2*>(&v[t].y));
                acc.x += a0.x; acc.y += a0.y; acc.z += a1.x; acc.w += a1.y;
            }
        }
    }

    // tail (< 32 edges)
    if (nfull < deg) {
        int m = deg - nfull;
        int s = (lane < m) ? g_csr[s0 + nfull + lane] : 0;
        for (int j = 0; j < m; j++) {
            int sj = __shfl_sync(0xffffffffu, s, j);
            uint2 hv = h2[(size_t)sj * 32 + lane];
            float2 a0 = __half22float2(*reinterpret_cast<const __half2*>(&hv.x));
            float2 a1 = __half22float2(*reinterpret_cast<const __half2*>(&hv.y));
            acc.x += a0.x; acc.y += a0.y; acc.z += a1.x; acc.w += a1.y;
        }
    }

    float4 bb = ((const float4*)b)[lane];
    float4 o;
    o.x = fmaxf(fmaf(di, acc.x, bb.x), 0.f);
    o.y = fmaxf(fmaf(di, acc.y, bb.y), 0.f);
    o.z = fmaxf(fmaf(di, acc.z, bb.z), 0.f);
    o.w = fmaxf(fmaf(di, acc.w, bb.w), 0.f);
    ((float4*)out)[(size_t)node * 32 + lane] = o;
}

// ---------------------------------------------------------------------------
extern "C" void kernel_launch(void* const* d_in, const int* in_sizes, int n_in,
                              void* d_out, int out_size) {
    const float* x   = (const float*)d_in[0];
    const void*  ei  = d_in[1];            // [2, E] int32 or int64 (probed)
    const float* W   = (const float*)d_in[2];
    const float* b   = (const float*)d_in[3];
    float*       out = (float*)d_out;

    const int n = in_sizes[0] / FDIM;      // 100000
    const int e = in_sizes[1] / 2;         // 3200000

    static cudaStream_t s1 = nullptr;
    static cudaEvent_t  ev_fork = nullptr, ev_res = nullptr, ev_scale = nullptr;
    if (s1 == nullptr) {
        cudaStreamCreateWithFlags(&s1, cudaStreamNonBlocking);
        cudaEventCreateWithFlags(&ev_fork,  cudaEventDisableTiming);
        cudaEventCreateWithFlags(&ev_res,   cudaEventDisableTiming);
        cudaEventCreateWithFlags(&ev_scale, cudaEventDisableTiming);
        cudaFuncSetAttribute(k_gemm_tf32, cudaFuncAttributeMaxDynamicSharedMemorySize,
                             64 * 1024);
    }

    // Fork at t=0: GEMM chain (no CSR dependencies) on s1
    cudaEventRecord(ev_fork, 0);
    cudaStreamWaitEvent(s1, ev_fork, 0);
    k_wprep<<<32, 256, 0, s1>>>(W);
    k_gemm_tf32<<<(n + 127) / 128, 256, 64 * 1024, s1>>>(x, n);

    // CSR chain on capture stream
    k_init<<<(n + 255) / 256, 256>>>(ei, n);
    int deg_threads = (e + 7) / 8;
    k_deg<<<(deg_threads + 255) / 256, 256>>>(ei, e, n);
    k_reserve<<<(n + 255) / 256, 256>>>(n);
    cudaEventRecord(ev_res, 0);

    // scale needs gemm (in-stream on s1) + reserve (event)
    cudaStreamWaitEvent(s1, ev_res, 0);
    int st = n * 16;
    k_scale<<<(st + 255) / 256, 256, 0, s1>>>(n);
    cudaEventRecord(ev_scale, s1);

    // fill runs concurrent with gemm/scale
    int fill_threads = (e + 3) / 4;
    k_fill<<<(fill_threads + 255) / 256, 256>>>(ei, e, n);

    // join: gather needs CSR (in-stream) + g_h (event)
    cudaStreamWaitEvent(0, ev_scale, 0);
    long long threads_total = (long long)n * 32;
    k_gather<<<(int)((threads_total + 255) / 256), 256>>>(b, out, n);
}